// round 7
// baseline (speedup 1.0000x reference)
#include <cuda_runtime.h>
#include <cuda_fp16.h>
#include <cstdint>
#include <math.h>

// Problem constants
#define B_BATCH 8
#define T_SEQ   2048
#define DIN     1024
#define DOUT    1024
#define M_TOTAL (B_BATCH * T_SEQ)   // 16384
#define GAMMA_F 0.9865f

// Scan chunking
#define NCH 64
#define CHUNK (T_SEQ / NCH)         // 32

// GEMM tiling: CTA 128x64, K-chunk 32 per stage (both GEMMs), 8 warps (4x2),
// warp tile 32x32. 2 CTAs/SM.
#define TILE_N 64
#define SMEM_STRIDE 40                       // fp16 elems/row (32+8 pad) = 80 B
#define A_TILE_B    (128 * SMEM_STRIDE * 2)  // 10240 bytes
#define B_TILE_B    (TILE_N * SMEM_STRIDE * 2) // 5120 bytes
#define AQ_OFF      0
#define BQ_OFF      10240
#define AS_OFF      15360
#define BS_OFF      25600
#define STAGE_BYTES 30720
#define NST 3
#define SMEM_TOTAL  (NST * STAGE_BYTES)      // 92160
#define NSTAGES 32                           // 32 k-chunks, both GEMMs per stage

// ---------------- device scratch ----------------
__device__ float g_wksum[DIN];
__device__ float g_ksum[M_TOTAL];
__device__ float g_carry[B_BATCH][NCH][DIN];
__device__ __half g_xq_hi[(size_t)M_TOTAL * DIN];
__device__ __half g_sv_hi[(size_t)M_TOTAL * DIN];
__device__ __half g_wqt_hi[(size_t)DIN * DOUT];   // [n][k]
__device__ __half g_wvt_hi[(size_t)DIN * DOUT];

// ---------------- helpers ----------------
__device__ __forceinline__ uint32_t smem_u32(const void* p) {
    uint32_t a;
    asm("{ .reg .u64 t; cvta.to.shared.u64 t, %1; cvt.u32.u64 %0, t; }" : "=r"(a) : "l"(p));
    return a;
}
__device__ __forceinline__ void cp16(uint32_t dst, const void* src) {
    asm volatile("cp.async.cg.shared.global [%0], [%1], 16;\n" :: "r"(dst), "l"(src));
}
__device__ __forceinline__ void ldsm_x4(uint32_t* r, uint32_t addr) {
    asm volatile("ldmatrix.sync.aligned.m8n8.x4.shared.b16 {%0,%1,%2,%3}, [%4];"
                 : "=r"(r[0]), "=r"(r[1]), "=r"(r[2]), "=r"(r[3]) : "r"(addr));
}
__device__ __forceinline__ void mma_f16(float* c, const uint32_t* a, const uint32_t* b) {
    asm volatile(
        "mma.sync.aligned.m16n8k16.row.col.f32.f16.f16.f32 "
        "{%0,%1,%2,%3},{%4,%5,%6,%7},{%8,%9},{%0,%1,%2,%3};\n"
        : "+f"(c[0]), "+f"(c[1]), "+f"(c[2]), "+f"(c[3])
        : "r"(a[0]), "r"(a[1]), "r"(a[2]), "r"(a[3]), "r"(b[0]), "r"(b[1]));
}

// ---------------- kernel 1: wksum[d] = sum_e Wk[d][e] ----------------
__global__ void wksum_kernel(const float* __restrict__ Wk) {
    int d = blockIdx.x;
    float s = 0.f;
    for (int e = threadIdx.x; e < DOUT; e += 256)
        s += Wk[(size_t)d * DOUT + e];
    __shared__ float red[256];
    red[threadIdx.x] = s;
    __syncthreads();
    for (int o = 128; o > 0; o >>= 1) {
        if (threadIdx.x < o) red[threadIdx.x] += red[threadIdx.x + o];
        __syncthreads();
    }
    if (threadIdx.x == 0) g_wksum[d] = red[0];
}

// ---------------- kernel 2 (fused prep): ksum; xq->fp16; W transpose->fp16 ----------------
__global__ void prep_kernel(const float* __restrict__ xk,
                            const float* __restrict__ xq,
                            const float* __restrict__ Wq,
                            const float* __restrict__ Wv) {
    int bx = blockIdx.x;
    int tid = threadIdx.x;
    __shared__ float tile[32][33];

    if (bx < 2048) {
        int warp = tid >> 5, lane = tid & 31;
        int m = bx * 8 + warp;
        const float4* row = (const float4*)(xk + (size_t)m * DIN);
        const float4* wk = (const float4*)g_wksum;
        float s = 0.f;
        #pragma unroll
        for (int it = 0; it < 8; it++) {
            float4 a = row[lane + it * 32], w = wk[lane + it * 32];
            s += a.x * w.x + a.y * w.y + a.z * w.z + a.w * w.w;
        }
        #pragma unroll
        for (int o = 16; o; o >>= 1)
            s += __shfl_xor_sync(0xFFFFFFFFu, s, o);
        if (lane == 0) {
            int t = m & (T_SEQ - 1);
            g_ksum[m] = (t == 0) ? 0.f : s;
        }
    } else if (bx < 18432) {
        size_t idx = (size_t)(bx - 2048) * 256 + tid;   // float4 index
        float4 v = ((const float4*)xq)[idx];
        __half h[4] = {__float2half_rn(v.x), __float2half_rn(v.y),
                       __float2half_rn(v.z), __float2half_rn(v.w)};
        ((uint2*)g_xq_hi)[idx] = *(uint2*)h;
    } else {
        int b = bx - 18432;
        const float* W = (b < 1024) ? Wq : Wv;
        __half* Th = (b < 1024) ? g_wqt_hi : g_wvt_hi;
        b &= 1023;
        int n0 = (b & 31) * 32, k0 = (b >> 5) * 32;
        int tx = tid & 31, ty = tid >> 5;
        for (int i = ty; i < 32; i += 8)
            tile[i][tx] = W[(size_t)(k0 + i) * DOUT + n0 + tx];
        __syncthreads();
        for (int i = ty; i < 32; i += 8)
            Th[(size_t)(n0 + i) * DIN + k0 + tx] = __float2half_rn(tile[tx][i]);
    }
}

// ---------------- kernel 3: per-chunk carries (float4 per thread) ----------------
__global__ void scan_carry(const float* __restrict__ xv) {
    int ch = blockIdx.x, b = blockIdx.y;
    int d0 = threadIdx.x * 4;
    const float* base = xv + ((size_t)b * T_SEQ + (size_t)ch * CHUNK) * DIN + d0;
    const float* ks = g_ksum + b * T_SEQ + ch * CHUNK;
    float s0 = 0.f, s1 = 0.f, s2 = 0.f, s3 = 0.f;
    #pragma unroll 8
    for (int t = 0; t < CHUNK; t++) {
        float4 v = *(const float4*)(base + (size_t)t * DIN);
        float k = ks[t];
        s0 = GAMMA_F * s0 + k * v.x;
        s1 = GAMMA_F * s1 + k * v.y;
        s2 = GAMMA_F * s2 + k * v.z;
        s3 = GAMMA_F * s3 + k * v.w;
    }
    *(float4*)&g_carry[b][ch][d0] = make_float4(s0, s1, s2, s3);
}

// ---------------- kernel 3.5: in-place exclusive prefix over chunk carries ----------------
// After: g_carry[b][ch][d] = state entering chunk ch (P[0]=0; P[ch]=gC*P[ch-1]+carry[ch-1])
__global__ void scan_mid(float gammaC) {
    int idx = blockIdx.x * 256 + threadIdx.x;    // 0..8191
    int b = idx >> 10, d = idx & 1023;
    float s = 0.f;
    #pragma unroll 8
    for (int ch = 0; ch < NCH; ch++) {
        float c = g_carry[b][ch][d];
        g_carry[b][ch][d] = s;
        s = s * gammaC + c;
    }
}

// ---------------- kernel 4: apply prefix + write sv (fp16) ----------------
__global__ void scan_apply(const float* __restrict__ xv) {
    int ch = blockIdx.x, b = blockIdx.y;
    int d0 = threadIdx.x * 4;
    float4 p = *(const float4*)&g_carry[b][ch][d0];
    float s0 = p.x, s1 = p.y, s2 = p.z, s3 = p.w;
    size_t base_off = ((size_t)b * T_SEQ + (size_t)ch * CHUNK) * DIN + d0;
    const float* base = xv + base_off;
    const float* ks = g_ksum + b * T_SEQ + ch * CHUNK;
    #pragma unroll 8
    for (int t = 0; t < CHUNK; t++) {
        float4 v = *(const float4*)(base + (size_t)t * DIN);
        float k = ks[t];
        s0 = GAMMA_F * s0 + k * v.x;
        s1 = GAMMA_F * s1 + k * v.y;
        s2 = GAMMA_F * s2 + k * v.z;
        s3 = GAMMA_F * s3 + k * v.w;
        __half h[4] = {__float2half_rn(s0), __float2half_rn(s1),
                       __float2half_rn(s2), __float2half_rn(s3)};
        *(uint2*)(g_sv_hi + base_off + (size_t)t * DIN) = *(uint2*)h;
    }
}

// ---------------- fused dual GEMM: O = (xq@Wq) .* (sv@Wv), pure fp16 ----------------
// CTA 128x64, 8 warps (wm=warp>>1 in 0..3, wn=warp&1), warp tile 32x32, 2 CTAs/SM.

__device__ __forceinline__ void load_tile_a(uint32_t sbase, const __half* g,
                                            int row0, int k0, int tid) {
    const char* gb = (const char*)(g + (size_t)row0 * DIN + k0);
    #pragma unroll
    for (int i = 0; i < 2; i++) {
        int slot = tid + i * 256;
        int r = slot >> 2, c = slot & 3;
        cp16(sbase + (uint32_t)(r * (SMEM_STRIDE * 2) + c * 16),
             gb + (size_t)r * (DIN * 2) + c * 16);
    }
}
__device__ __forceinline__ void load_tile_b(uint32_t sbase, const __half* g,
                                            int n0, int k0, int tid) {
    const char* gb = (const char*)(g + (size_t)n0 * DIN + k0);
    int r = tid >> 2, c = tid & 3;     // 64 rows x 4 chunks
    cp16(sbase + (uint32_t)(r * (SMEM_STRIDE * 2) + c * 16),
         gb + (size_t)r * (DIN * 2) + c * 16);
}

__device__ __forceinline__ void mma_pass(uint32_t Abase, uint32_t Bbase,
                                         float acc[2][4][4], int wm, int wn, int lane) {
    const int arow = lane & 15;
    const int acol8 = (lane >> 4) * 8;
    const int bnrow = ((lane >> 4) & 1) * 8 + (lane & 7);
    const int bcol8 = ((lane >> 3) & 1) * 8;

    #pragma unroll
    for (int kk = 0; kk < 32; kk += 16) {
        uint32_t ah[2][4], bh[4][2];
        #pragma unroll
        for (int i = 0; i < 2; i++) {
            uint32_t aoff = (uint32_t)((wm * 32 + i * 16 + arow) * (SMEM_STRIDE * 2)
                                       + (kk + acol8) * 2);
            ldsm_x4(ah[i], Abase + aoff);
        }
        #pragma unroll
        for (int j0 = 0; j0 < 4; j0 += 2) {
            uint32_t boff = (uint32_t)((wn * 32 + j0 * 8 + bnrow) * (SMEM_STRIDE * 2)
                                       + (kk + bcol8) * 2);
            uint32_t br[4];
            ldsm_x4(br, Bbase + boff);
            bh[j0][0] = br[0]; bh[j0][1] = br[1];
            bh[j0 + 1][0] = br[2]; bh[j0 + 1][1] = br[3];
        }
        #pragma unroll
        for (int i = 0; i < 2; i++)
            #pragma unroll
            for (int j = 0; j < 4; j++)
                mma_f16(acc[i][j], ah[i], bh[j]);
    }
}

__global__ __launch_bounds__(256, 2) void qs_gemm(float* __restrict__ out) {
    extern __shared__ char smem[];
    uint32_t sb = smem_u32(smem);
    const int tid = threadIdx.x;
    const int warp = tid >> 5, lane = tid & 31;
    const int wm = warp >> 1, wn = warp & 1;
    const int g = lane >> 2, tg = lane & 3;
    const int row0 = blockIdx.y * 128;
    const int n0 = blockIdx.x * TILE_N;

    float accQ[2][4][4], accS[2][4][4];
    #pragma unroll
    for (int i = 0; i < 2; i++)
        #pragma unroll
        for (int j = 0; j < 4; j++)
            #pragma unroll
            for (int k = 0; k < 4; k++) { accQ[i][j][k] = 0.f; accS[i][j][k] = 0.f; }

    auto issue = [&](int s) {
        if (s < NSTAGES) {
            int k0 = s * 32;
            uint32_t bufb = sb + (uint32_t)(s % NST) * STAGE_BYTES;
            load_tile_a(bufb + AQ_OFF, g_xq_hi,  row0, k0, tid);
            load_tile_b(bufb + BQ_OFF, g_wqt_hi, n0,  k0, tid);
            load_tile_a(bufb + AS_OFF, g_sv_hi,  row0, k0, tid);
            load_tile_b(bufb + BS_OFF, g_wvt_hi, n0,  k0, tid);
        }
        asm volatile("cp.async.commit_group;\n" ::: "memory");
    };

    issue(0);
    issue(1);

    for (int s = 0; s < NSTAGES; s++) {
        asm volatile("cp.async.wait_group 1;\n" ::: "memory");
        __syncthreads();
        issue(s + 2);
        uint32_t bufb = sb + (uint32_t)(s % NST) * STAGE_BYTES;
        mma_pass(bufb + AQ_OFF, bufb + BQ_OFF, accQ, wm, wn, lane);
        mma_pass(bufb + AS_OFF, bufb + BS_OFF, accS, wm, wn, lane);
    }

    // epilogue: O = Q .* S
    #pragma unroll
    for (int i = 0; i < 2; i++) {
        #pragma unroll
        for (int j = 0; j < 4; j++) {
            int r = row0 + wm * 32 + i * 16;
            int c = n0 + wn * 32 + j * 8 + 2 * tg;
            float2 o0, o1;
            o0.x = accQ[i][j][0] * accS[i][j][0];
            o0.y = accQ[i][j][1] * accS[i][j][1];
            o1.x = accQ[i][j][2] * accS[i][j][2];
            o1.y = accQ[i][j][3] * accS[i][j][3];
            *(float2*)(out + (size_t)(r + g    ) * DOUT + c) = o0;
            *(float2*)(out + (size_t)(r + g + 8) * DOUT + c) = o1;
        }
    }
}

// ---------------- launch ----------------
extern "C" void kernel_launch(void* const* d_in, const int* in_sizes, int n_in,
                              void* d_out, int out_size)
{
    const float* xq = (const float*)d_in[0];
    const float* xk = (const float*)d_in[1];
    const float* xv = (const float*)d_in[2];
    const float* Wq = (const float*)d_in[3];
    const float* Wk = (const float*)d_in[4];
    const float* Wv = (const float*)d_in[5];
    float* out = (float*)d_out;

    float gammaC = (float)pow((double)GAMMA_F, (double)CHUNK);

    cudaFuncSetAttribute(qs_gemm, cudaFuncAttributeMaxDynamicSharedMemorySize, SMEM_TOTAL);

    wksum_kernel<<<DIN, 256>>>(Wk);                                   // 1
    prep_kernel<<<20480, 256>>>(xk, xq, Wq, Wv);                      // 2
    scan_carry<<<dim3(NCH, B_BATCH), 256>>>(xv);                      // 3
    scan_mid<<<32, 256>>>(gammaC);                                    // 4
    scan_apply<<<dim3(NCH, B_BATCH), 256>>>(xv);                      // 5
    qs_gemm<<<dim3(DOUT / TILE_N, M_TOTAL / 128), 256, SMEM_TOTAL>>>(out); // 6
}

// round 8
// speedup vs baseline: 1.1677x; 1.1677x over previous
#include <cuda_runtime.h>
#include <cuda_fp16.h>
#include <cstdint>
#include <math.h>

// Problem constants
#define B_BATCH 8
#define T_SEQ   2048
#define DIN     1024
#define DOUT    1024
#define M_TOTAL (B_BATCH * T_SEQ)   // 16384
#define GAMMA_F 0.9865f

// Scan chunking
#define NCH 64
#define CHUNK (T_SEQ / NCH)         // 32

// GEMM tiling: CTA 128x128, K-chunk 64 per stage (both GEMMs), 8 warps (2x4),
// warp tile 64x32.
#define KCHUNK 64
#define SMEM_STRIDE 72                        // fp16 elems/row (64+8 pad) = 144 B
#define TILE_B      (128 * SMEM_STRIDE * 2)   // 18432 bytes
#define AQ_OFF      0
#define BQ_OFF      18432
#define AS_OFF      36864
#define BS_OFF      55296
#define STAGE_BYTES 73728
#define NST 3
#define SMEM_TOTAL  (NST * STAGE_BYTES)       // 221184 (< 227 KB limit)
#define NSTAGES 16                            // 16 k-chunks, both GEMMs per stage

// ---------------- device scratch ----------------
__device__ float g_wksum[DIN];
__device__ float g_ksum[M_TOTAL];
__device__ float g_carry[B_BATCH][NCH][DIN];
__device__ __half g_xq_hi[(size_t)M_TOTAL * DIN];
__device__ __half g_sv_hi[(size_t)M_TOTAL * DIN];
__device__ __half g_wqt_hi[(size_t)DIN * DOUT];   // [n][k]
__device__ __half g_wvt_hi[(size_t)DIN * DOUT];

// ---------------- helpers ----------------
__device__ __forceinline__ uint32_t smem_u32(const void* p) {
    uint32_t a;
    asm("{ .reg .u64 t; cvta.to.shared.u64 t, %1; cvt.u32.u64 %0, t; }" : "=r"(a) : "l"(p));
    return a;
}
__device__ __forceinline__ void cp16(uint32_t dst, const void* src) {
    asm volatile("cp.async.cg.shared.global [%0], [%1], 16;\n" :: "r"(dst), "l"(src));
}
__device__ __forceinline__ void ldsm_x4(uint32_t* r, uint32_t addr) {
    asm volatile("ldmatrix.sync.aligned.m8n8.x4.shared.b16 {%0,%1,%2,%3}, [%4];"
                 : "=r"(r[0]), "=r"(r[1]), "=r"(r[2]), "=r"(r[3]) : "r"(addr));
}
__device__ __forceinline__ void mma_f16(float* c, const uint32_t* a, const uint32_t* b) {
    asm volatile(
        "mma.sync.aligned.m16n8k16.row.col.f32.f16.f16.f32 "
        "{%0,%1,%2,%3},{%4,%5,%6,%7},{%8,%9},{%0,%1,%2,%3};\n"
        : "+f"(c[0]), "+f"(c[1]), "+f"(c[2]), "+f"(c[3])
        : "r"(a[0]), "r"(a[1]), "r"(a[2]), "r"(a[3]), "r"(b[0]), "r"(b[1]));
}

// ---------------- kernel 1: wksum[d] = sum_e Wk[d][e] ----------------
__global__ void wksum_kernel(const float* __restrict__ Wk) {
    int d = blockIdx.x;
    float s = 0.f;
    for (int e = threadIdx.x; e < DOUT; e += 256)
        s += Wk[(size_t)d * DOUT + e];
    __shared__ float red[256];
    red[threadIdx.x] = s;
    __syncthreads();
    for (int o = 128; o > 0; o >>= 1) {
        if (threadIdx.x < o) red[threadIdx.x] += red[threadIdx.x + o];
        __syncthreads();
    }
    if (threadIdx.x == 0) g_wksum[d] = red[0];
}

// ---------------- kernel 2 (fused prep): ksum; xq->fp16; W transpose->fp16 ----------------
__global__ void prep_kernel(const float* __restrict__ xk,
                            const float* __restrict__ xq,
                            const float* __restrict__ Wq,
                            const float* __restrict__ Wv) {
    int bx = blockIdx.x;
    int tid = threadIdx.x;
    __shared__ float tile[32][33];

    if (bx < 2048) {
        int warp = tid >> 5, lane = tid & 31;
        int m = bx * 8 + warp;
        const float4* row = (const float4*)(xk + (size_t)m * DIN);
        const float4* wk = (const float4*)g_wksum;
        float s = 0.f;
        #pragma unroll
        for (int it = 0; it < 8; it++) {
            float4 a = row[lane + it * 32], w = wk[lane + it * 32];
            s += a.x * w.x + a.y * w.y + a.z * w.z + a.w * w.w;
        }
        #pragma unroll
        for (int o = 16; o; o >>= 1)
            s += __shfl_xor_sync(0xFFFFFFFFu, s, o);
        if (lane == 0) {
            int t = m & (T_SEQ - 1);
            g_ksum[m] = (t == 0) ? 0.f : s;
        }
    } else if (bx < 18432) {
        size_t idx = (size_t)(bx - 2048) * 256 + tid;   // float4 index
        float4 v = ((const float4*)xq)[idx];
        __half h[4] = {__float2half_rn(v.x), __float2half_rn(v.y),
                       __float2half_rn(v.z), __float2half_rn(v.w)};
        ((uint2*)g_xq_hi)[idx] = *(uint2*)h;
    } else {
        int b = bx - 18432;
        const float* W = (b < 1024) ? Wq : Wv;
        __half* Th = (b < 1024) ? g_wqt_hi : g_wvt_hi;
        b &= 1023;
        int n0 = (b & 31) * 32, k0 = (b >> 5) * 32;
        int tx = tid & 31, ty = tid >> 5;
        for (int i = ty; i < 32; i += 8)
            tile[i][tx] = W[(size_t)(k0 + i) * DOUT + n0 + tx];
        __syncthreads();
        for (int i = ty; i < 32; i += 8)
            Th[(size_t)(n0 + i) * DIN + k0 + tx] = __float2half_rn(tile[tx][i]);
    }
}

// ---------------- kernel 3: per-chunk carries (float4 per thread) ----------------
__global__ void scan_carry(const float* __restrict__ xv) {
    int ch = blockIdx.x, b = blockIdx.y;
    int d0 = threadIdx.x * 4;
    const float* base = xv + ((size_t)b * T_SEQ + (size_t)ch * CHUNK) * DIN + d0;
    const float* ks = g_ksum + b * T_SEQ + ch * CHUNK;
    float s0 = 0.f, s1 = 0.f, s2 = 0.f, s3 = 0.f;
    #pragma unroll 8
    for (int t = 0; t < CHUNK; t++) {
        float4 v = *(const float4*)(base + (size_t)t * DIN);
        float k = ks[t];
        s0 = GAMMA_F * s0 + k * v.x;
        s1 = GAMMA_F * s1 + k * v.y;
        s2 = GAMMA_F * s2 + k * v.z;
        s3 = GAMMA_F * s3 + k * v.w;
    }
    *(float4*)&g_carry[b][ch][d0] = make_float4(s0, s1, s2, s3);
}

// ---------------- kernel 3.5: in-place exclusive prefix over chunk carries ----------------
// Batched loads (MLP ~64) -> register chain -> batched stores.
__global__ void scan_mid(float gammaC) {
    int idx = blockIdx.x * 256 + threadIdx.x;    // 0..8191
    int b = idx >> 10, d = idx & 1023;
    float c[NCH];
    #pragma unroll
    for (int ch = 0; ch < NCH; ch++)
        c[ch] = g_carry[b][ch][d];
    float s = 0.f;
    #pragma unroll
    for (int ch = 0; ch < NCH; ch++) {
        float t = c[ch];
        c[ch] = s;
        s = s * gammaC + t;
    }
    #pragma unroll
    for (int ch = 0; ch < NCH; ch++)
        g_carry[b][ch][d] = c[ch];
}

// ---------------- kernel 4: apply prefix + write sv (fp16), 8 lanes/thread ----------------
__global__ void scan_apply(const float* __restrict__ xv) {
    int ch = blockIdx.x, b = blockIdx.y;
    int d0 = threadIdx.x * 8;
    float4 p0 = *(const float4*)&g_carry[b][ch][d0];
    float4 p1 = *(const float4*)&g_carry[b][ch][d0 + 4];
    float s0 = p0.x, s1 = p0.y, s2 = p0.z, s3 = p0.w;
    float s4 = p1.x, s5 = p1.y, s6 = p1.z, s7 = p1.w;
    size_t base_off = ((size_t)b * T_SEQ + (size_t)ch * CHUNK) * DIN + d0;
    const float* base = xv + base_off;
    const float* ks = g_ksum + b * T_SEQ + ch * CHUNK;
    #pragma unroll 4
    for (int t = 0; t < CHUNK; t++) {
        float4 v0 = *(const float4*)(base + (size_t)t * DIN);
        float4 v1 = *(const float4*)(base + (size_t)t * DIN + 4);
        float k = ks[t];
        s0 = GAMMA_F * s0 + k * v0.x;
        s1 = GAMMA_F * s1 + k * v0.y;
        s2 = GAMMA_F * s2 + k * v0.z;
        s3 = GAMMA_F * s3 + k * v0.w;
        s4 = GAMMA_F * s4 + k * v1.x;
        s5 = GAMMA_F * s5 + k * v1.y;
        s6 = GAMMA_F * s6 + k * v1.z;
        s7 = GAMMA_F * s7 + k * v1.w;
        __half h[8] = {__float2half_rn(s0), __float2half_rn(s1),
                       __float2half_rn(s2), __float2half_rn(s3),
                       __float2half_rn(s4), __float2half_rn(s5),
                       __float2half_rn(s6), __float2half_rn(s7)};
        *(uint4*)(g_sv_hi + base_off + (size_t)t * DIN) = *(uint4*)h;
    }
}

// ---------------- fused dual GEMM: O = (xq@Wq) .* (sv@Wv), pure fp16 ----------------
// CTA 128x128, KCHUNK=64, 8 warps (2x4), warp tile 64x32, 3-stage pipeline.

__device__ __forceinline__ void load_tile_f16(uint32_t sbase, const __half* g,
                                              int row0, int k0, int tid) {
    const char* gb = (const char*)(g + (size_t)row0 * DIN + k0);
    #pragma unroll
    for (int i = 0; i < 4; i++) {
        int slot = tid + i * 256;            // 0..1023
        int r = slot >> 3, c = slot & 7;     // 8 x 16B chunks per 128B row
        cp16(sbase + (uint32_t)(r * (SMEM_STRIDE * 2) + c * 16),
             gb + (size_t)r * (DIN * 2) + c * 16);
    }
}

__device__ __forceinline__ void mma_pass(uint32_t Abase, uint32_t Bbase,
                                         float acc[4][4][4], int wm, int wn, int lane) {
    const int arow = lane & 15;
    const int acol8 = (lane >> 4) * 8;
    const int bnrow = ((lane >> 4) & 1) * 8 + (lane & 7);
    const int bcol8 = ((lane >> 3) & 1) * 8;

    #pragma unroll
    for (int kk = 0; kk < KCHUNK; kk += 16) {
        uint32_t ah[4][4], bh[4][2];
        #pragma unroll
        for (int i = 0; i < 4; i++) {
            uint32_t aoff = (uint32_t)((wm * 64 + i * 16 + arow) * (SMEM_STRIDE * 2)
                                       + (kk + acol8) * 2);
            ldsm_x4(ah[i], Abase + aoff);
        }
        #pragma unroll
        for (int j0 = 0; j0 < 4; j0 += 2) {
            uint32_t boff = (uint32_t)((wn * 32 + j0 * 8 + bnrow) * (SMEM_STRIDE * 2)
                                       + (kk + bcol8) * 2);
            uint32_t br[4];
            ldsm_x4(br, Bbase + boff);
            bh[j0][0] = br[0]; bh[j0][1] = br[1];
            bh[j0 + 1][0] = br[2]; bh[j0 + 1][1] = br[3];
        }
        #pragma unroll
        for (int i = 0; i < 4; i++)
            #pragma unroll
            for (int j = 0; j < 4; j++)
                mma_f16(acc[i][j], ah[i], bh[j]);
    }
}

__global__ __launch_bounds__(256, 1) void qs_gemm(float* __restrict__ out) {
    extern __shared__ char smem[];
    uint32_t sb = smem_u32(smem);
    const int tid = threadIdx.x;
    const int warp = tid >> 5, lane = tid & 31;
    const int wm = warp >> 2, wn = warp & 3;
    const int g = lane >> 2, tg = lane & 3;
    const int row0 = blockIdx.y * 128;
    const int n0 = blockIdx.x * 128;

    float accQ[4][4][4], accS[4][4][4];
    #pragma unroll
    for (int i = 0; i < 4; i++)
        #pragma unroll
        for (int j = 0; j < 4; j++)
            #pragma unroll
            for (int k = 0; k < 4; k++) { accQ[i][j][k] = 0.f; accS[i][j][k] = 0.f; }

    auto issue = [&](int s) {
        if (s < NSTAGES) {
            int k0 = s * KCHUNK;
            uint32_t bufb = sb + (uint32_t)(s % NST) * STAGE_BYTES;
            load_tile_f16(bufb + AQ_OFF, g_xq_hi,  row0, k0, tid);
            load_tile_f16(bufb + BQ_OFF, g_wqt_hi, n0,  k0, tid);
            load_tile_f16(bufb + AS_OFF, g_sv_hi,  row0, k0, tid);
            load_tile_f16(bufb + BS_OFF, g_wvt_hi, n0,  k0, tid);
        }
        asm volatile("cp.async.commit_group;\n" ::: "memory");
    };

    issue(0);
    issue(1);

    for (int s = 0; s < NSTAGES; s++) {
        asm volatile("cp.async.wait_group 1;\n" ::: "memory");
        __syncthreads();
        issue(s + 2);
        uint32_t bufb = sb + (uint32_t)(s % NST) * STAGE_BYTES;
        mma_pass(bufb + AQ_OFF, bufb + BQ_OFF, accQ, wm, wn, lane);
        mma_pass(bufb + AS_OFF, bufb + BS_OFF, accS, wm, wn, lane);
    }

    // epilogue: O = Q .* S
    #pragma unroll
    for (int i = 0; i < 4; i++) {
        #pragma unroll
        for (int j = 0; j < 4; j++) {
            int r = row0 + wm * 64 + i * 16;
            int c = n0 + wn * 32 + j * 8 + 2 * tg;
            float2 o0, o1;
            o0.x = accQ[i][j][0] * accS[i][j][0];
            o0.y = accQ[i][j][1] * accS[i][j][1];
            o1.x = accQ[i][j][2] * accS[i][j][2];
            o1.y = accQ[i][j][3] * accS[i][j][3];
            *(float2*)(out + (size_t)(r + g    ) * DOUT + c) = o0;
            *(float2*)(out + (size_t)(r + g + 8) * DOUT + c) = o1;
        }
    }
}

// ---------------- launch ----------------
extern "C" void kernel_launch(void* const* d_in, const int* in_sizes, int n_in,
                              void* d_out, int out_size)
{
    const float* xq = (const float*)d_in[0];
    const float* xk = (const float*)d_in[1];
    const float* xv = (const float*)d_in[2];
    const float* Wq = (const float*)d_in[3];
    const float* Wk = (const float*)d_in[4];
    const float* Wv = (const float*)d_in[5];
    float* out = (float*)d_out;

    float gammaC = (float)pow((double)GAMMA_F, (double)CHUNK);

    cudaFuncSetAttribute(qs_gemm, cudaFuncAttributeMaxDynamicSharedMemorySize, SMEM_TOTAL);

    wksum_kernel<<<DIN, 256>>>(Wk);                                   // 1
    prep_kernel<<<20480, 256>>>(xk, xq, Wq, Wv);                      // 2
    scan_carry<<<dim3(NCH, B_BATCH), 256>>>(xv);                      // 3
    scan_mid<<<32, 256>>>(gammaC);                                    // 4
    scan_apply<<<dim3(NCH, B_BATCH), 128>>>(xv);                      // 5
    qs_gemm<<<dim3(DOUT / 128, M_TOTAL / 128), 256, SMEM_TOTAL>>>(out); // 6
}

// round 9
// speedup vs baseline: 1.1945x; 1.0229x over previous
#include <cuda_runtime.h>
#include <cuda_fp16.h>
#include <cstdint>
#include <math.h>

// Problem constants
#define B_BATCH 8
#define T_SEQ   2048
#define DIN     1024
#define DOUT    1024
#define M_TOTAL (B_BATCH * T_SEQ)   // 16384
#define GAMMA_F 0.9865f

// Scan chunking
#define NCH 64
#define CHUNK (T_SEQ / NCH)         // 32

// GEMM tiling: CTA 128x128, K-chunk 64 per stage (both GEMMs), 8 warps (2x4),
// warp tile 64x32.
#define KCHUNK 64
#define SMEM_STRIDE 72                        // fp16 elems/row (64+8 pad) = 144 B
#define TILE_B      (128 * SMEM_STRIDE * 2)   // 18432 bytes
#define AQ_OFF      0
#define BQ_OFF      18432
#define AS_OFF      36864
#define BS_OFF      55296
#define STAGE_BYTES 73728
#define NST 3
#define SMEM_TOTAL  (NST * STAGE_BYTES)       // 221184 (< 227 KB limit)
#define NSTAGES 16                            // 16 k-chunks, both GEMMs per stage

// ---------------- device scratch ----------------
__device__ float g_wksum[DIN];
__device__ float g_ksum[M_TOTAL];
__device__ float g_carry[B_BATCH][NCH][DIN];
__device__ __half g_xq_hi[(size_t)M_TOTAL * DIN];
__device__ __half g_sv_hi[(size_t)M_TOTAL * DIN];
__device__ __half g_wqt_hi[(size_t)DIN * DOUT];   // [n][k]
__device__ __half g_wvt_hi[(size_t)DIN * DOUT];

// ---------------- helpers ----------------
__device__ __forceinline__ uint32_t smem_u32(const void* p) {
    uint32_t a;
    asm("{ .reg .u64 t; cvta.to.shared.u64 t, %1; cvt.u32.u64 %0, t; }" : "=r"(a) : "l"(p));
    return a;
}
__device__ __forceinline__ void cp16(uint32_t dst, const void* src) {
    asm volatile("cp.async.cg.shared.global [%0], [%1], 16;\n" :: "r"(dst), "l"(src));
}
__device__ __forceinline__ void ldsm_x4(uint32_t* r, uint32_t addr) {
    asm volatile("ldmatrix.sync.aligned.m8n8.x4.shared.b16 {%0,%1,%2,%3}, [%4];"
                 : "=r"(r[0]), "=r"(r[1]), "=r"(r[2]), "=r"(r[3]) : "r"(addr));
}
__device__ __forceinline__ void mma_f16(float* c, const uint32_t* a, const uint32_t* b) {
    asm volatile(
        "mma.sync.aligned.m16n8k16.row.col.f32.f16.f16.f32 "
        "{%0,%1,%2,%3},{%4,%5,%6,%7},{%8,%9},{%0,%1,%2,%3};\n"
        : "+f"(c[0]), "+f"(c[1]), "+f"(c[2]), "+f"(c[3])
        : "r"(a[0]), "r"(a[1]), "r"(a[2]), "r"(a[3]), "r"(b[0]), "r"(b[1]));
}

// ---------------- kernel 1: wksum[d] = sum_e Wk[d][e] ----------------
__global__ void wksum_kernel(const float* __restrict__ Wk) {
    int d = blockIdx.x;
    float s = 0.f;
    for (int e = threadIdx.x; e < DOUT; e += 256)
        s += Wk[(size_t)d * DOUT + e];
    __shared__ float red[256];
    red[threadIdx.x] = s;
    __syncthreads();
    for (int o = 128; o > 0; o >>= 1) {
        if (threadIdx.x < o) red[threadIdx.x] += red[threadIdx.x + o];
        __syncthreads();
    }
    if (threadIdx.x == 0) g_wksum[d] = red[0];
}

// ---------------- kernel B (side stream): xq->fp16; W transpose->fp16 ----------------
// blocks [0,16384):      xq -> fp16
// blocks [16384,17408):  Wq transpose
// blocks [17408,18432):  Wv transpose
__global__ void prep_kernel(const float* __restrict__ xq,
                            const float* __restrict__ Wq,
                            const float* __restrict__ Wv) {
    int bx = blockIdx.x;
    int tid = threadIdx.x;
    __shared__ float tile[32][33];

    if (bx < 16384) {
        size_t idx = (size_t)bx * 256 + tid;   // float4 index
        float4 v = ((const float4*)xq)[idx];
        __half h[4] = {__float2half_rn(v.x), __float2half_rn(v.y),
                       __float2half_rn(v.z), __float2half_rn(v.w)};
        ((uint2*)g_xq_hi)[idx] = *(uint2*)h;
    } else {
        int b = bx - 16384;
        const float* W = (b < 1024) ? Wq : Wv;
        __half* Th = (b < 1024) ? g_wqt_hi : g_wvt_hi;
        b &= 1023;
        int n0 = (b & 31) * 32, k0 = (b >> 5) * 32;
        int tx = tid & 31, ty = tid >> 5;
        for (int i = ty; i < 32; i += 8)
            tile[i][tx] = W[(size_t)(k0 + i) * DOUT + n0 + tx];
        __syncthreads();
        for (int i = ty; i < 32; i += 8)
            Th[(size_t)(n0 + i) * DIN + k0 + tx] = __float2half_rn(tile[tx][i]);
    }
}

// ---------------- kernel 2: merged ksum + per-chunk carries ----------------
// Each (ch,b) block: compute ksum for its 32 t-rows (xk . wksum), stash in
// smem + g_ksum, then run the chunk-local recurrence over xv.
__global__ void scan_carry(const float* __restrict__ xk,
                           const float* __restrict__ xv) {
    int ch = blockIdx.x, b = blockIdx.y;
    int t0 = ch * CHUNK;
    __shared__ float ks[CHUNK];
    int warp = threadIdx.x >> 5, lane = threadIdx.x & 31;

    // 8 warps x 4 rows each
    #pragma unroll
    for (int rr = 0; rr < 4; rr++) {
        int t = warp * 4 + rr;
        const float4* row = (const float4*)(xk + ((size_t)b * T_SEQ + t0 + t) * DIN);
        const float4* wk = (const float4*)g_wksum;
        float s = 0.f;
        #pragma unroll
        for (int it = 0; it < 8; it++) {
            float4 a = row[lane + it * 32], w = wk[lane + it * 32];
            s += a.x * w.x + a.y * w.y + a.z * w.z + a.w * w.w;
        }
        #pragma unroll
        for (int o = 16; o; o >>= 1)
            s += __shfl_xor_sync(0xFFFFFFFFu, s, o);
        if (lane == 0) {
            float val = (t0 + t == 0) ? 0.f : s;
            ks[t] = val;
            g_ksum[b * T_SEQ + t0 + t] = val;
        }
    }
    __syncthreads();

    int d0 = threadIdx.x * 4;
    const float* base = xv + ((size_t)b * T_SEQ + t0) * DIN + d0;
    float s0 = 0.f, s1 = 0.f, s2 = 0.f, s3 = 0.f;
    #pragma unroll 8
    for (int t = 0; t < CHUNK; t++) {
        float4 v = *(const float4*)(base + (size_t)t * DIN);
        float k = ks[t];
        s0 = GAMMA_F * s0 + k * v.x;
        s1 = GAMMA_F * s1 + k * v.y;
        s2 = GAMMA_F * s2 + k * v.z;
        s3 = GAMMA_F * s3 + k * v.w;
    }
    *(float4*)&g_carry[b][ch][d0] = make_float4(s0, s1, s2, s3);
}

// ---------------- kernel 3: in-place exclusive prefix over chunk carries ----------------
__global__ void scan_mid(float gammaC) {
    int idx = blockIdx.x * 256 + threadIdx.x;    // 0..8191
    int b = idx >> 10, d = idx & 1023;
    float c[NCH];
    #pragma unroll
    for (int ch = 0; ch < NCH; ch++)
        c[ch] = g_carry[b][ch][d];
    float s = 0.f;
    #pragma unroll
    for (int ch = 0; ch < NCH; ch++) {
        float t = c[ch];
        c[ch] = s;
        s = s * gammaC + t;
    }
    #pragma unroll
    for (int ch = 0; ch < NCH; ch++)
        g_carry[b][ch][d] = c[ch];
}

// ---------------- kernel 4: apply prefix + write sv (fp16), 8 lanes/thread ----------------
__global__ void scan_apply(const float* __restrict__ xv) {
    int ch = blockIdx.x, b = blockIdx.y;
    int d0 = threadIdx.x * 8;
    float4 p0 = *(const float4*)&g_carry[b][ch][d0];
    float4 p1 = *(const float4*)&g_carry[b][ch][d0 + 4];
    float s0 = p0.x, s1 = p0.y, s2 = p0.z, s3 = p0.w;
    float s4 = p1.x, s5 = p1.y, s6 = p1.z, s7 = p1.w;
    size_t base_off = ((size_t)b * T_SEQ + (size_t)ch * CHUNK) * DIN + d0;
    const float* base = xv + base_off;
    const float* ks = g_ksum + b * T_SEQ + ch * CHUNK;
    #pragma unroll 4
    for (int t = 0; t < CHUNK; t++) {
        float4 v0 = *(const float4*)(base + (size_t)t * DIN);
        float4 v1 = *(const float4*)(base + (size_t)t * DIN + 4);
        float k = ks[t];
        s0 = GAMMA_F * s0 + k * v0.x;
        s1 = GAMMA_F * s1 + k * v0.y;
        s2 = GAMMA_F * s2 + k * v0.z;
        s3 = GAMMA_F * s3 + k * v0.w;
        s4 = GAMMA_F * s4 + k * v1.x;
        s5 = GAMMA_F * s5 + k * v1.y;
        s6 = GAMMA_F * s6 + k * v1.z;
        s7 = GAMMA_F * s7 + k * v1.w;
        __half h[8] = {__float2half_rn(s0), __float2half_rn(s1),
                       __float2half_rn(s2), __float2half_rn(s3),
                       __float2half_rn(s4), __float2half_rn(s5),
                       __float2half_rn(s6), __float2half_rn(s7)};
        *(uint4*)(g_sv_hi + base_off + (size_t)t * DIN) = *(uint4*)h;
    }
}

// ---------------- fused dual GEMM: O = (xq@Wq) .* (sv@Wv), pure fp16 ----------------

__device__ __forceinline__ void load_tile_f16(uint32_t sbase, const __half* g,
                                              int row0, int k0, int tid) {
    const char* gb = (const char*)(g + (size_t)row0 * DIN + k0);
    #pragma unroll
    for (int i = 0; i < 4; i++) {
        int slot = tid + i * 256;            // 0..1023
        int r = slot >> 3, c = slot & 7;     // 8 x 16B chunks per 128B row
        cp16(sbase + (uint32_t)(r * (SMEM_STRIDE * 2) + c * 16),
             gb + (size_t)r * (DIN * 2) + c * 16);
    }
}

__device__ __forceinline__ void mma_pass(uint32_t Abase, uint32_t Bbase,
                                         float acc[4][4][4], int wm, int wn, int lane) {
    const int arow = lane & 15;
    const int acol8 = (lane >> 4) * 8;
    const int bnrow = ((lane >> 4) & 1) * 8 + (lane & 7);
    const int bcol8 = ((lane >> 3) & 1) * 8;

    #pragma unroll
    for (int kk = 0; kk < KCHUNK; kk += 16) {
        uint32_t ah[4][4], bh[4][2];
        #pragma unroll
        for (int i = 0; i < 4; i++) {
            uint32_t aoff = (uint32_t)((wm * 64 + i * 16 + arow) * (SMEM_STRIDE * 2)
                                       + (kk + acol8) * 2);
            ldsm_x4(ah[i], Abase + aoff);
        }
        #pragma unroll
        for (int j0 = 0; j0 < 4; j0 += 2) {
            uint32_t boff = (uint32_t)((wn * 32 + j0 * 8 + bnrow) * (SMEM_STRIDE * 2)
                                       + (kk + bcol8) * 2);
            uint32_t br[4];
            ldsm_x4(br, Bbase + boff);
            bh[j0][0] = br[0]; bh[j0][1] = br[1];
            bh[j0 + 1][0] = br[2]; bh[j0 + 1][1] = br[3];
        }
        #pragma unroll
        for (int i = 0; i < 4; i++)
            #pragma unroll
            for (int j = 0; j < 4; j++)
                mma_f16(acc[i][j], ah[i], bh[j]);
    }
}

__global__ __launch_bounds__(256, 1) void qs_gemm(float* __restrict__ out) {
    extern __shared__ char smem[];
    uint32_t sb = smem_u32(smem);
    const int tid = threadIdx.x;
    const int warp = tid >> 5, lane = tid & 31;
    const int wm = warp >> 2, wn = warp & 3;
    const int g = lane >> 2, tg = lane & 3;
    const int row0 = blockIdx.y * 128;
    const int n0 = blockIdx.x * 128;

    float accQ[4][4][4], accS[4][4][4];
    #pragma unroll
    for (int i = 0; i < 4; i++)
        #pragma unroll
        for (int j = 0; j < 4; j++)
            #pragma unroll
            for (int k = 0; k < 4; k++) { accQ[i][j][k] = 0.f; accS[i][j][k] = 0.f; }

    auto issue = [&](int s) {
        if (s < NSTAGES) {
            int k0 = s * KCHUNK;
            uint32_t bufb = sb + (uint32_t)(s % NST) * STAGE_BYTES;
            load_tile_f16(bufb + AQ_OFF, g_xq_hi,  row0, k0, tid);
            load_tile_f16(bufb + BQ_OFF, g_wqt_hi, n0,  k0, tid);
            load_tile_f16(bufb + AS_OFF, g_sv_hi,  row0, k0, tid);
            load_tile_f16(bufb + BS_OFF, g_wvt_hi, n0,  k0, tid);
        }
        asm volatile("cp.async.commit_group;\n" ::: "memory");
    };

    issue(0);
    issue(1);

    for (int s = 0; s < NSTAGES; s++) {
        asm volatile("cp.async.wait_group 1;\n" ::: "memory");
        __syncthreads();
        issue(s + 2);
        uint32_t bufb = sb + (uint32_t)(s % NST) * STAGE_BYTES;
        mma_pass(bufb + AQ_OFF, bufb + BQ_OFF, accQ, wm, wn, lane);
        mma_pass(bufb + AS_OFF, bufb + BS_OFF, accS, wm, wn, lane);
    }

    // epilogue: O = Q .* S
    #pragma unroll
    for (int i = 0; i < 4; i++) {
        #pragma unroll
        for (int j = 0; j < 4; j++) {
            int r = row0 + wm * 64 + i * 16;
            int c = n0 + wn * 32 + j * 8 + 2 * tg;
            float2 o0, o1;
            o0.x = accQ[i][j][0] * accS[i][j][0];
            o0.y = accQ[i][j][1] * accS[i][j][1];
            o1.x = accQ[i][j][2] * accS[i][j][2];
            o1.y = accQ[i][j][3] * accS[i][j][3];
            *(float2*)(out + (size_t)(r + g    ) * DOUT + c) = o0;
            *(float2*)(out + (size_t)(r + g + 8) * DOUT + c) = o1;
        }
    }
}

// ---------------- launch ----------------
extern "C" void kernel_launch(void* const* d_in, const int* in_sizes, int n_in,
                              void* d_out, int out_size)
{
    const float* xq = (const float*)d_in[0];
    const float* xk = (const float*)d_in[1];
    const float* xv = (const float*)d_in[2];
    const float* Wq = (const float*)d_in[3];
    const float* Wk = (const float*)d_in[4];
    const float* Wv = (const float*)d_in[5];
    float* out = (float*)d_out;

    float gammaC = (float)pow((double)GAMMA_F, (double)CHUNK);

    cudaFuncSetAttribute(qs_gemm, cudaFuncAttributeMaxDynamicSharedMemorySize, SMEM_TOTAL);

    // Side stream + events for the independent prep chain. Created once
    // (host-side resources only; no device allocation).
    static cudaStream_t s2 = nullptr;
    static cudaEvent_t evFork = nullptr, evJoin = nullptr;
    if (s2 == nullptr) {
        cudaStreamCreateWithFlags(&s2, cudaStreamNonBlocking);
        cudaEventCreateWithFlags(&evFork, cudaEventDisableTiming);
        cudaEventCreateWithFlags(&evJoin, cudaEventDisableTiming);
    }

    // Fork: prep (xq conversion + W transposes) runs concurrently with the
    // scan chain; both join before the GEMM.
    cudaEventRecord(evFork, 0);
    cudaStreamWaitEvent(s2, evFork, 0);
    prep_kernel<<<18432, 256, 0, s2>>>(xq, Wq, Wv);
    cudaEventRecord(evJoin, s2);

    // Critical chain on the main (capturing) stream.
    wksum_kernel<<<DIN, 256>>>(Wk);
    scan_carry<<<dim3(NCH, B_BATCH), 256>>>(xk, xv);
    scan_mid<<<32, 256>>>(gammaC);
    scan_apply<<<dim3(NCH, B_BATCH), 128>>>(xv);

    cudaStreamWaitEvent(0, evJoin, 0);
    qs_gemm<<<dim3(DOUT / 128, M_TOTAL / 128), 256, SMEM_TOTAL>>>(out);
}

// round 10
// speedup vs baseline: 1.2161x; 1.0181x over previous
#include <cuda_runtime.h>
#include <cuda_fp16.h>
#include <cstdint>
#include <math.h>

// Problem constants
#define B_BATCH 8
#define T_SEQ   2048
#define DIN     1024
#define DOUT    1024
#define M_TOTAL (B_BATCH * T_SEQ)   // 16384
#define GAMMA_F 0.9865f

// Scan chunking
#define NCH 64
#define CHUNK (T_SEQ / NCH)         // 32

// GEMM tiling: CTA 128x128, K-chunk 64, 8 warps (2x4), warp tile 64x32.
// Split kernels (single GEMM each): stage = {A, B} tiles, 2 CTAs/SM.
#define KCHUNK 64
#define SMEM_STRIDE 72                        // fp16 elems/row (64+8 pad) = 144 B
#define TILE_B      (128 * SMEM_STRIDE * 2)   // 18432 bytes
#define A_OFF       0
#define B_OFF       18432
#define STAGE_BYTES 36864
#define NST 3
#define SMEM_TOTAL  (NST * STAGE_BYTES)       // 110592 (x2 CTAs = 221184 < 228KB)
#define NSTAGES 16                            // 16 k-chunks

// ---------------- device scratch ----------------
__device__ float g_wksum[DIN];
__device__ float g_ksum[M_TOTAL];
__device__ float g_carry[B_BATCH][NCH][DIN];
__device__ float g_q[(size_t)M_TOTAL * DOUT];     // 64 MB fp32 Q scratch
__device__ __half g_xq_hi[(size_t)M_TOTAL * DIN];
__device__ __half g_sv_hi[(size_t)M_TOTAL * DIN];
__device__ __half g_wqt_hi[(size_t)DIN * DOUT];   // [n][k]
__device__ __half g_wvt_hi[(size_t)DIN * DOUT];

// ---------------- helpers ----------------
__device__ __forceinline__ uint32_t smem_u32(const void* p) {
    uint32_t a;
    asm("{ .reg .u64 t; cvta.to.shared.u64 t, %1; cvt.u32.u64 %0, t; }" : "=r"(a) : "l"(p));
    return a;
}
__device__ __forceinline__ void cp16(uint32_t dst, const void* src) {
    asm volatile("cp.async.cg.shared.global [%0], [%1], 16;\n" :: "r"(dst), "l"(src));
}
__device__ __forceinline__ void ldsm_x4(uint32_t* r, uint32_t addr) {
    asm volatile("ldmatrix.sync.aligned.m8n8.x4.shared.b16 {%0,%1,%2,%3}, [%4];"
                 : "=r"(r[0]), "=r"(r[1]), "=r"(r[2]), "=r"(r[3]) : "r"(addr));
}
__device__ __forceinline__ void mma_f16(float* c, const uint32_t* a, const uint32_t* b) {
    asm volatile(
        "mma.sync.aligned.m16n8k16.row.col.f32.f16.f16.f32 "
        "{%0,%1,%2,%3},{%4,%5,%6,%7},{%8,%9},{%0,%1,%2,%3};\n"
        : "+f"(c[0]), "+f"(c[1]), "+f"(c[2]), "+f"(c[3])
        : "r"(a[0]), "r"(a[1]), "r"(a[2]), "r"(a[3]), "r"(b[0]), "r"(b[1]));
}

// ---------------- kernel 1: wksum[d] = sum_e Wk[d][e] ----------------
__global__ void wksum_kernel(const float* __restrict__ Wk) {
    int d = blockIdx.x;
    float s = 0.f;
    for (int e = threadIdx.x; e < DOUT; e += 256)
        s += Wk[(size_t)d * DOUT + e];
    __shared__ float red[256];
    red[threadIdx.x] = s;
    __syncthreads();
    for (int o = 128; o > 0; o >>= 1) {
        if (threadIdx.x < o) red[threadIdx.x] += red[threadIdx.x + o];
        __syncthreads();
    }
    if (threadIdx.x == 0) g_wksum[d] = red[0];
}

// ---------------- kernel B (side stream): xq->fp16; W transpose->fp16 ----------------
__global__ void prep_kernel(const float* __restrict__ xq,
                            const float* __restrict__ Wq,
                            const float* __restrict__ Wv) {
    int bx = blockIdx.x;
    int tid = threadIdx.x;
    __shared__ float tile[32][33];

    if (bx < 16384) {
        size_t idx = (size_t)bx * 256 + tid;   // float4 index
        float4 v = ((const float4*)xq)[idx];
        __half h[4] = {__float2half_rn(v.x), __float2half_rn(v.y),
                       __float2half_rn(v.z), __float2half_rn(v.w)};
        ((uint2*)g_xq_hi)[idx] = *(uint2*)h;
    } else {
        int b = bx - 16384;
        const float* W = (b < 1024) ? Wq : Wv;
        __half* Th = (b < 1024) ? g_wqt_hi : g_wvt_hi;
        b &= 1023;
        int n0 = (b & 31) * 32, k0 = (b >> 5) * 32;
        int tx = tid & 31, ty = tid >> 5;
        for (int i = ty; i < 32; i += 8)
            tile[i][tx] = W[(size_t)(k0 + i) * DOUT + n0 + tx];
        __syncthreads();
        for (int i = ty; i < 32; i += 8)
            Th[(size_t)(n0 + i) * DIN + k0 + tx] = __float2half_rn(tile[tx][i]);
    }
}

// ---------------- kernel 2: merged ksum + per-chunk carries ----------------
__global__ void scan_carry(const float* __restrict__ xk,
                           const float* __restrict__ xv) {
    int ch = blockIdx.x, b = blockIdx.y;
    int t0 = ch * CHUNK;
    __shared__ float ks[CHUNK];
    int warp = threadIdx.x >> 5, lane = threadIdx.x & 31;

    #pragma unroll
    for (int rr = 0; rr < 4; rr++) {
        int t = warp * 4 + rr;
        const float4* row = (const float4*)(xk + ((size_t)b * T_SEQ + t0 + t) * DIN);
        const float4* wk = (const float4*)g_wksum;
        float s = 0.f;
        #pragma unroll
        for (int it = 0; it < 8; it++) {
            float4 a = row[lane + it * 32], w = wk[lane + it * 32];
            s += a.x * w.x + a.y * w.y + a.z * w.z + a.w * w.w;
        }
        #pragma unroll
        for (int o = 16; o; o >>= 1)
            s += __shfl_xor_sync(0xFFFFFFFFu, s, o);
        if (lane == 0) {
            float val = (t0 + t == 0) ? 0.f : s;
            ks[t] = val;
            g_ksum[b * T_SEQ + t0 + t] = val;
        }
    }
    __syncthreads();

    int d0 = threadIdx.x * 4;
    const float* base = xv + ((size_t)b * T_SEQ + t0) * DIN + d0;
    float s0 = 0.f, s1 = 0.f, s2 = 0.f, s3 = 0.f;
    #pragma unroll 8
    for (int t = 0; t < CHUNK; t++) {
        float4 v = *(const float4*)(base + (size_t)t * DIN);
        float k = ks[t];
        s0 = GAMMA_F * s0 + k * v.x;
        s1 = GAMMA_F * s1 + k * v.y;
        s2 = GAMMA_F * s2 + k * v.z;
        s3 = GAMMA_F * s3 + k * v.w;
    }
    *(float4*)&g_carry[b][ch][d0] = make_float4(s0, s1, s2, s3);
}

// ---------------- kernel 3: in-place exclusive prefix over chunk carries ----------------
__global__ void scan_mid(float gammaC) {
    int idx = blockIdx.x * 256 + threadIdx.x;    // 0..8191
    int b = idx >> 10, d = idx & 1023;
    float c[NCH];
    #pragma unroll
    for (int ch = 0; ch < NCH; ch++)
        c[ch] = g_carry[b][ch][d];
    float s = 0.f;
    #pragma unroll
    for (int ch = 0; ch < NCH; ch++) {
        float t = c[ch];
        c[ch] = s;
        s = s * gammaC + t;
    }
    #pragma unroll
    for (int ch = 0; ch < NCH; ch++)
        g_carry[b][ch][d] = c[ch];
}

// ---------------- kernel 4: apply prefix + write sv (fp16), 8 lanes/thread ----------------
__global__ void scan_apply(const float* __restrict__ xv) {
    int ch = blockIdx.x, b = blockIdx.y;
    int d0 = threadIdx.x * 8;
    float4 p0 = *(const float4*)&g_carry[b][ch][d0];
    float4 p1 = *(const float4*)&g_carry[b][ch][d0 + 4];
    float s0 = p0.x, s1 = p0.y, s2 = p0.z, s3 = p0.w;
    float s4 = p1.x, s5 = p1.y, s6 = p1.z, s7 = p1.w;
    size_t base_off = ((size_t)b * T_SEQ + (size_t)ch * CHUNK) * DIN + d0;
    const float* base = xv + base_off;
    const float* ks = g_ksum + b * T_SEQ + ch * CHUNK;
    #pragma unroll 4
    for (int t = 0; t < CHUNK; t++) {
        float4 v0 = *(const float4*)(base + (size_t)t * DIN);
        float4 v1 = *(const float4*)(base + (size_t)t * DIN + 4);
        float k = ks[t];
        s0 = GAMMA_F * s0 + k * v0.x;
        s1 = GAMMA_F * s1 + k * v0.y;
        s2 = GAMMA_F * s2 + k * v0.z;
        s3 = GAMMA_F * s3 + k * v0.w;
        s4 = GAMMA_F * s4 + k * v1.x;
        s5 = GAMMA_F * s5 + k * v1.y;
        s6 = GAMMA_F * s6 + k * v1.z;
        s7 = GAMMA_F * s7 + k * v1.w;
        __half h[8] = {__float2half_rn(s0), __float2half_rn(s1),
                       __float2half_rn(s2), __float2half_rn(s3),
                       __float2half_rn(s4), __float2half_rn(s5),
                       __float2half_rn(s6), __float2half_rn(s7)};
        *(uint4*)(g_sv_hi + base_off + (size_t)t * DIN) = *(uint4*)h;
    }
}

// ---------------- split GEMMs ----------------
// qgemm: g_q = xq@Wq (fp32 scratch).  sgemm: out = g_q .* (sv@Wv).

__device__ __forceinline__ void load_tile_f16(uint32_t sbase, const __half* g,
                                              int row0, int k0, int tid) {
    const char* gb = (const char*)(g + (size_t)row0 * DIN + k0);
    #pragma unroll
    for (int i = 0; i < 4; i++) {
        int slot = tid + i * 256;            // 0..1023
        int r = slot >> 3, c = slot & 7;     // 8 x 16B chunks per 128B row
        cp16(sbase + (uint32_t)(r * (SMEM_STRIDE * 2) + c * 16),
             gb + (size_t)r * (DIN * 2) + c * 16);
    }
}

__device__ __forceinline__ void mma_pass(uint32_t Abase, uint32_t Bbase,
                                         float acc[4][4][4], int wm, int wn, int lane) {
    const int arow = lane & 15;
    const int acol8 = (lane >> 4) * 8;
    const int bnrow = ((lane >> 4) & 1) * 8 + (lane & 7);
    const int bcol8 = ((lane >> 3) & 1) * 8;

    #pragma unroll
    for (int kk = 0; kk < KCHUNK; kk += 16) {
        uint32_t ah[4][4], bh[4][2];
        #pragma unroll
        for (int i = 0; i < 4; i++) {
            uint32_t aoff = (uint32_t)((wm * 64 + i * 16 + arow) * (SMEM_STRIDE * 2)
                                       + (kk + acol8) * 2);
            ldsm_x4(ah[i], Abase + aoff);
        }
        #pragma unroll
        for (int j0 = 0; j0 < 4; j0 += 2) {
            uint32_t boff = (uint32_t)((wn * 32 + j0 * 8 + bnrow) * (SMEM_STRIDE * 2)
                                       + (kk + bcol8) * 2);
            uint32_t br[4];
            ldsm_x4(br, Bbase + boff);
            bh[j0][0] = br[0]; bh[j0][1] = br[1];
            bh[j0 + 1][0] = br[2]; bh[j0 + 1][1] = br[3];
        }
        #pragma unroll
        for (int i = 0; i < 4; i++)
            #pragma unroll
            for (int j = 0; j < 4; j++)
                mma_f16(acc[i][j], ah[i], bh[j]);
    }
}

// shared mainloop body; MULT=0 -> write acc; MULT=1 -> multiply by g_q, write out
template <int MULT>
__device__ __forceinline__ void gemm_body(const __half* Aglob, const __half* Bglob,
                                          float* dst) {
    extern __shared__ char smem[];
    uint32_t sb = smem_u32(smem);
    const int tid = threadIdx.x;
    const int warp = tid >> 5, lane = tid & 31;
    const int wm = warp >> 2, wn = warp & 3;
    const int g = lane >> 2, tg = lane & 3;
    const int row0 = blockIdx.y * 128;
    const int n0 = blockIdx.x * 128;

    float acc[4][4][4];
    #pragma unroll
    for (int i = 0; i < 4; i++)
        #pragma unroll
        for (int j = 0; j < 4; j++)
            #pragma unroll
            for (int k = 0; k < 4; k++) acc[i][j][k] = 0.f;

    auto issue = [&](int s) {
        if (s < NSTAGES) {
            int k0 = s * KCHUNK;
            uint32_t bufb = sb + (uint32_t)(s % NST) * STAGE_BYTES;
            load_tile_f16(bufb + A_OFF, Aglob, row0, k0, tid);
            load_tile_f16(bufb + B_OFF, Bglob, n0,  k0, tid);
        }
        asm volatile("cp.async.commit_group;\n" ::: "memory");
    };

    issue(0);
    issue(1);

    for (int s = 0; s < NSTAGES; s++) {
        asm volatile("cp.async.wait_group 1;\n" ::: "memory");
        __syncthreads();
        issue(s + 2);
        uint32_t bufb = sb + (uint32_t)(s % NST) * STAGE_BYTES;
        mma_pass(bufb + A_OFF, bufb + B_OFF, acc, wm, wn, lane);
    }

    #pragma unroll
    for (int i = 0; i < 4; i++) {
        #pragma unroll
        for (int j = 0; j < 4; j++) {
            int r = row0 + wm * 64 + i * 16;
            int c = n0 + wn * 32 + j * 8 + 2 * tg;
            size_t o0 = (size_t)(r + g    ) * DOUT + c;
            size_t o1 = (size_t)(r + g + 8) * DOUT + c;
            float2 v0 = make_float2(acc[i][j][0], acc[i][j][1]);
            float2 v1 = make_float2(acc[i][j][2], acc[i][j][3]);
            if (MULT) {
                float2 q0 = *(const float2*)(g_q + o0);
                float2 q1 = *(const float2*)(g_q + o1);
                v0.x *= q0.x; v0.y *= q0.y;
                v1.x *= q1.x; v1.y *= q1.y;
            }
            *(float2*)(dst + o0) = v0;
            *(float2*)(dst + o1) = v1;
        }
    }
}

__global__ __launch_bounds__(256, 2) void qgemm() {
    gemm_body<0>(g_xq_hi, g_wqt_hi, g_q);
}
__global__ __launch_bounds__(256, 2) void sgemm(float* __restrict__ out) {
    gemm_body<1>(g_sv_hi, g_wvt_hi, out);
}

// ---------------- launch ----------------
extern "C" void kernel_launch(void* const* d_in, const int* in_sizes, int n_in,
                              void* d_out, int out_size)
{
    const float* xq = (const float*)d_in[0];
    const float* xk = (const float*)d_in[1];
    const float* xv = (const float*)d_in[2];
    const float* Wq = (const float*)d_in[3];
    const float* Wk = (const float*)d_in[4];
    const float* Wv = (const float*)d_in[5];
    float* out = (float*)d_out;

    float gammaC = (float)pow((double)GAMMA_F, (double)CHUNK);

    cudaFuncSetAttribute(qgemm, cudaFuncAttributeMaxDynamicSharedMemorySize, SMEM_TOTAL);
    cudaFuncSetAttribute(sgemm, cudaFuncAttributeMaxDynamicSharedMemorySize, SMEM_TOTAL);

    static cudaStream_t s2 = nullptr;
    static cudaEvent_t evFork = nullptr, evJoin = nullptr;
    if (s2 == nullptr) {
        cudaStreamCreateWithFlags(&s2, cudaStreamNonBlocking);
        cudaEventCreateWithFlags(&evFork, cudaEventDisableTiming);
        cudaEventCreateWithFlags(&evJoin, cudaEventDisableTiming);
    }

    // Side stream: prep then Q-GEMM (independent of the scan chain).
    cudaEventRecord(evFork, 0);
    cudaStreamWaitEvent(s2, evFork, 0);
    prep_kernel<<<18432, 256, 0, s2>>>(xq, Wq, Wv);
    qgemm<<<dim3(DOUT / 128, M_TOTAL / 128), 256, SMEM_TOTAL, s2>>>();
    cudaEventRecord(evJoin, s2);

    // Critical chain on the main (capturing) stream.
    wksum_kernel<<<DIN, 256>>>(Wk);
    scan_carry<<<dim3(NCH, B_BATCH), 256>>>(xk, xv);
    scan_mid<<<32, 256>>>(gammaC);
    scan_apply<<<dim3(NCH, B_BATCH), 128>>>(xv);

    // Join: S-GEMM needs sv (main) and g_q (side).
    cudaStreamWaitEvent(0, evJoin, 0);
    sgemm<<<dim3(DOUT / 128, M_TOTAL / 128), 256, SMEM_TOTAL>>>(out);
}